// round 14
// baseline (speedup 1.0000x reference)
#include <cuda_runtime.h>
#include <cuda_bf16.h>
#include <math.h>

#define BB 64
#define LL 1024
#define HH 64
#define H2 128
#define VV 32000
#define TOK 64
#define HPAD 68

// Scratch (device globals; no allocation allowed; zero-initialized)
__device__ float  g_kall[BB * LL * HH];   // 16 MB
__device__ float4 g_meta[BB * LL];        // (rinv, 0.16*kk, D(t,t+1), D(t,t+2))
__device__ float  g_d3[BB * LL];          // D(t, t+3)
__device__ float  g_r2[BB * HH];

// ---------------------------------------------------------------------------
// Kernel 1: per-token front-end (round-12 WIN config: 256 thr, 64 tok,
// reusable weight buffer, 2 blocks/SM) — unchanged.
// ---------------------------------------------------------------------------
__global__ void __launch_bounds__(256, 2) k1_frontend(
        const int* __restrict__ seq, const float* __restrict__ embed,
        const float* __restrict__ W1, const float* __restrict__ b1,
        const float* __restrict__ W2, const float* __restrict__ b2,
        const float* __restrict__ gamma, const float* __restrict__ beta,
        const float* __restrict__ kpW) {
    extern __shared__ float sm[];
    float* h_sm = sm;                      // TOK * HPAD
    float* u_sm = h_sm + TOK * HPAD;       // 64 * 128
    float* wbuf = u_sm + TOK * H2;         // 8192 (W1 / W2 / kpW)
    float* b1s  = wbuf + HH * H2;          // 128
    float* b2s  = b1s + H2;                // 64
    float* gsm  = b2s + HH;                // 64
    float* bsm  = gsm + HH;                // 64

    const int tid  = threadIdx.x;
    const int tok0 = blockIdx.x * TOK;

    if (tid < H2) b1s[tid] = b1[tid];
    if (tid < HH) { b2s[tid] = b2[tid]; gsm[tid] = gamma[tid]; bsm[tid] = beta[tid]; }
    {
        const float4* w4 = (const float4*)W1;
        float4* d4 = (float4*)wbuf;
        #pragma unroll
        for (int k = 0; k < 8; k++) d4[tid + 256 * k] = w4[tid + 256 * k];
    }
    #pragma unroll
    for (int k = 0; k < 16; k++) {
        int idx = tid + 256 * k;
        int t = idx >> 6, j = idx & 63;
        int row = seq[tok0 + t];
        h_sm[t * HPAD + j] = embed[row * HH + j];
    }
    __syncthreads();

    const int tt = tid >> 4;
    const int ct = tid & 15;

    // GEMM1
    {
        const int r0 = tt * 4, c0 = ct * 8;
        float acc[4][8];
        #pragma unroll
        for (int r = 0; r < 4; r++)
            #pragma unroll
            for (int c = 0; c < 8; c++) acc[r][c] = 0.f;
        #pragma unroll 2
        for (int j4 = 0; j4 < HH; j4 += 4) {
            float hv[4][4];
            #pragma unroll
            for (int r = 0; r < 4; r++)
                *(float4*)hv[r] = *(const float4*)&h_sm[(r0 + r) * HPAD + j4];
            #pragma unroll
            for (int jj = 0; jj < 4; jj++) {
                float4 wA = *(const float4*)&wbuf[(j4 + jj) * H2 + c0];
                float4 wB = *(const float4*)&wbuf[(j4 + jj) * H2 + c0 + 4];
                #pragma unroll
                for (int r = 0; r < 4; r++) {
                    float hvv = hv[r][jj];
                    acc[r][0] = fmaf(hvv, wA.x, acc[r][0]);
                    acc[r][1] = fmaf(hvv, wA.y, acc[r][1]);
                    acc[r][2] = fmaf(hvv, wA.z, acc[r][2]);
                    acc[r][3] = fmaf(hvv, wA.w, acc[r][3]);
                    acc[r][4] = fmaf(hvv, wB.x, acc[r][4]);
                    acc[r][5] = fmaf(hvv, wB.y, acc[r][5]);
                    acc[r][6] = fmaf(hvv, wB.z, acc[r][6]);
                    acc[r][7] = fmaf(hvv, wB.w, acc[r][7]);
                }
            }
        }
        #pragma unroll
        for (int r = 0; r < 4; r++)
            #pragma unroll
            for (int c = 0; c < 8; c++)
                u_sm[(r0 + r) * H2 + c0 + c] = fmaxf(acc[r][c] + b1s[c0 + c], 0.f);
    }
    __syncthreads();

    // load W2 over W1
    {
        const float4* w4 = (const float4*)W2;
        float4* d4 = (float4*)wbuf;
        #pragma unroll
        for (int k = 0; k < 8; k++) d4[tid + 256 * k] = w4[tid + 256 * k];
    }
    __syncthreads();

    // GEMM2 + residual
    {
        const int r0 = tt * 4, c0 = ct * 4;
        float acc[4][4];
        #pragma unroll
        for (int r = 0; r < 4; r++)
            #pragma unroll
            for (int c = 0; c < 4; c++) acc[r][c] = 0.f;
        #pragma unroll 2
        for (int j4 = 0; j4 < H2; j4 += 4) {
            float uv[4][4];
            #pragma unroll
            for (int r = 0; r < 4; r++)
                *(float4*)uv[r] = *(const float4*)&u_sm[(r0 + r) * H2 + j4];
            #pragma unroll
            for (int jj = 0; jj < 4; jj++) {
                float4 w = *(const float4*)&wbuf[(j4 + jj) * HH + c0];
                #pragma unroll
                for (int r = 0; r < 4; r++) {
                    float uvv = uv[r][jj];
                    acc[r][0] = fmaf(uvv, w.x, acc[r][0]);
                    acc[r][1] = fmaf(uvv, w.y, acc[r][1]);
                    acc[r][2] = fmaf(uvv, w.z, acc[r][2]);
                    acc[r][3] = fmaf(uvv, w.w, acc[r][3]);
                }
            }
        }
        #pragma unroll
        for (int r = 0; r < 4; r++)
            #pragma unroll
            for (int c = 0; c < 4; c++)
                h_sm[(r0 + r) * HPAD + c0 + c] += acc[r][c] + b2s[c0 + c];
    }
    __syncthreads();

    // LN (4 threads/token) + load kpW
    {
        const int tq  = tid >> 2;
        const int sub = tid & 3;
        const int j0  = sub * 16;
        float s = 0.f, ss = 0.f;
        #pragma unroll 4
        for (int j = j0; j < j0 + 16; j++) {
            float x = h_sm[tq * HPAD + j];
            s += x; ss += x * x;
        }
        s  += __shfl_xor_sync(0xffffffffu, s, 1);
        ss += __shfl_xor_sync(0xffffffffu, ss, 1);
        s  += __shfl_xor_sync(0xffffffffu, s, 2);
        ss += __shfl_xor_sync(0xffffffffu, ss, 2);
        float mu = s * (1.f / HH);
        float var = ss * (1.f / HH) - mu * mu;
        float rs = rsqrtf(var + 1e-5f);
        #pragma unroll 4
        for (int j = j0; j < j0 + 16; j++) {
            float x = h_sm[tq * HPAD + j];
            h_sm[tq * HPAD + j] = (x - mu) * rs * gsm[j] + bsm[j];
        }
        const float4* w4 = (const float4*)kpW;
        float4* d4 = (float4*)wbuf;
        #pragma unroll
        for (int k = 0; k < 4; k++) d4[tid + 256 * k] = w4[tid + 256 * k];
    }
    __syncthreads();

    // GEMM3 -> g_kall
    {
        const int r0 = tt * 4, c0 = ct * 4;
        float acc[4][4];
        #pragma unroll
        for (int r = 0; r < 4; r++)
            #pragma unroll
            for (int c = 0; c < 4; c++) acc[r][c] = 0.f;
        #pragma unroll 2
        for (int j4 = 0; j4 < HH; j4 += 4) {
            float hv[4][4];
            #pragma unroll
            for (int r = 0; r < 4; r++)
                *(float4*)hv[r] = *(const float4*)&h_sm[(r0 + r) * HPAD + j4];
            #pragma unroll
            for (int jj = 0; jj < 4; jj++) {
                float4 w = *(const float4*)&wbuf[(j4 + jj) * HH + c0];
                #pragma unroll
                for (int r = 0; r < 4; r++) {
                    float hvv = hv[r][jj];
                    acc[r][0] = fmaf(hvv, w.x, acc[r][0]);
                    acc[r][1] = fmaf(hvv, w.y, acc[r][1]);
                    acc[r][2] = fmaf(hvv, w.z, acc[r][2]);
                    acc[r][3] = fmaf(hvv, w.w, acc[r][3]);
                }
            }
        }
        #pragma unroll
        for (int r = 0; r < 4; r++)
            #pragma unroll
            for (int c = 0; c < 4; c++)
                g_kall[(tok0 + r0 + r) * HH + c0 + c] = acc[r][c];
    }
}

// ---------------------------------------------------------------------------
// Kernel 1b: per-(b,t): g_meta = (rinv, 0.16*kk, D(t,t+1), D(t,t+2)),
//            g_d3 = D(t,t+3).
// ---------------------------------------------------------------------------
__global__ void k1b_meta() {
    const int g    = blockIdx.x * 8 + (threadIdx.x >> 5);
    const int lane = threadIdx.x & 31;
    const int b = g >> 10, t = g & 1023;
    if (t >= LL - 1) return;
    const float* kt = g_kall + (b * LL + t) * HH;
    float2 k0 = *(const float2*)&kt[lane * 2];
    float2 k1 = *(const float2*)&kt[HH + lane * 2];
    float2 k2v = make_float2(0.f, 0.f);
    float2 k3v = make_float2(0.f, 0.f);
    if (t + 2 <= LL - 1) k2v = *(const float2*)&kt[2 * HH + lane * 2];
    if (t + 3 <= LL - 1) k3v = *(const float2*)&kt[3 * HH + lane * 2];
    float pkk = k0.x * k0.x + k0.y * k0.y;
    float pd1 = k0.x * k1.x + k0.y * k1.y;
    float pd2 = k0.x * k2v.x + k0.y * k2v.y;
    float pd3 = k0.x * k3v.x + k0.y * k3v.y;
    #pragma unroll
    for (int off = 16; off; off >>= 1) {
        pkk += __shfl_xor_sync(0xffffffffu, pkk, off);
        pd1 += __shfl_xor_sync(0xffffffffu, pd1, off);
        pd2 += __shfl_xor_sync(0xffffffffu, pd2, off);
        pd3 += __shfl_xor_sync(0xffffffffu, pd3, off);
    }
    if (lane == 0) {
        float rinv = 1.0f / fmaxf(sqrtf(pkk), 1e-12f);
        g_meta[b * LL + t] = make_float4(rinv, 0.16f * pkk, pd1, pd2);
        g_d3[b * LL + t] = pd3;
    }
}

// ---------------------------------------------------------------------------
// Kernel 2: TWO-STEP fused scan. One 3-value butterfly + ONE barrier per two
// steps. Pending updates (t-2, t-1) applied fused with the two matvecs
// (M_{t-1}@k^{t+2}, M_{t-1}@k^{t+3}). Gates for t and t+1 both resolved from
// one reduction: ||err_{t+1}||^2 = B - 2cC + c^2 A, c = rinv1*rinv0*D(t,t+1).
// ---------------------------------------------------------------------------
__global__ void __launch_bounds__(64, 1) k2_scan(const float* __restrict__ rpW,
                                                 const float* __restrict__ rpb) {
    const int b = blockIdx.x;
    const int i = threadIdx.x;
    const int w = i >> 5;
    __shared__ __align__(16) float kbuf[8][64];
    __shared__ __align__(16) float4 wsum[2][2];   // [parity][warp] = (A,B,C,-)
    __shared__ float wsum2[2];                    // trailing step
    __shared__ float rds[64];

    float M[64];
    #pragma unroll
    for (int j = 0; j < 64; j++) M[j] = 0.f;

    const float*  kb = g_kall + b * LL * HH;
    const float4* mb = g_meta + b * LL;
    const float*  db = g_d3  + b * LL;

    // zero ring (slots 4..7 read as k^{t-2}/k^{t-1} with gs=0 early on)
    #pragma unroll
    for (int sl = 0; sl < 8; sl++) kbuf[sl][i] = 0.f;

    float kc0 = kb[i];                // k^t_i   (t=0)
    float kc1 = kb[HH + i];           // k^{t+1}_i
    float xA  = kb[2 * HH + i];       // k^{t+2}_i
    float xB  = kb[3 * HH + i];       // k^{t+3}_i
    kbuf[0][i] = kc0;
    kbuf[1][i] = kc1;
    kbuf[2][i] = xA;
    kbuf[3][i] = xB;

    float4 mA = make_float4(0.f, 0.f, 0.f, 0.f);  // meta[t-2]
    float4 mB = make_float4(0.f, 0.f, 0.f, 0.f);  // meta[t-1]
    float4 m0 = mb[0];                            // meta[t]
    float4 m1 = mb[1];                            // meta[t+1]
    float  d3p = 0.f;                             // D(t-2, t+1)
    float  a0 = 0.f, a1 = 0.f;                    // M_{t-3}@k^t, M_{t-3}@k^{t+1}
    float  gsA = 0.f, gsB = 0.f;                  // gs_{t-2,i}, gs_{t-1,i}
    __syncthreads();

    for (int t = 0; t < LL - 2; t += 2) {
        const int par = (t >> 1) & 1;
        // prefetches for t+4 / t+5 and meta pipeline
        float y0 = (t + 4 <= LL - 1) ? kb[(t + 4) * HH + i] : 0.f;
        float y1 = (t + 5 <= LL - 1) ? kb[(t + 5) * HH + i] : 0.f;
        float4 mN0 = mb[t + 2];
        float4 mN1 = mb[t + 3];       // mb[1023] is zero-init, never consumed
        float  d3n = db[t];           // D(t, t+3) -> next iteration's d3p

        // per-thread errors for steps t and t+1 (critical chain)
        float vpk0 = fmaf(gsA, mA.w, fmaf(gsB, mB.z, a0));
        float err0 = fmaf(-m0.x, vpk0, kc0);
        float vpk1 = fmaf(gsA, d3p, fmaf(gsB, mB.w, a1));
        float e0   = fmaf(-m1.x, vpk1, kc1);

        float pA = err0 * err0, pB = e0 * e0, pC = err0 * e0;
        #pragma unroll
        for (int off = 16; off; off >>= 1) {
            pA += __shfl_xor_sync(0xffffffffu, pA, off);
            pB += __shfl_xor_sync(0xffffffffu, pB, off);
            pC += __shfl_xor_sync(0xffffffffu, pC, off);
        }
        if ((i & 31) == 0) wsum[par][w] = make_float4(pA, pB, pC, 0.f);

        // publish k^{t+4}, k^{t+5} (overwrite dead slots t-4, t-3)
        kbuf[(t + 4) & 7][i] = y0;
        kbuf[(t + 5) & 7][i] = y1;

        // fused: apply pending updates (t-2, t-1), matvec vs k^{t+2}, k^{t+3}
        {
            const float* kpA = kbuf[(t - 2) & 7];   // valid pre-publish slots
            const float* kpB = kbuf[(t - 1) & 7];
            const float* knA = kbuf[(t + 2) & 7];
            const float* knB = kbuf[(t + 3) & 7];
            float v0 = 0.f, v1 = 0.f, v2 = 0.f, v3 = 0.f;
            float u0 = 0.f, u1 = 0.f, u2 = 0.f, u3 = 0.f;
            #pragma unroll
            for (int j = 0; j < 64; j += 4) {
                float4 pA4 = *(const float4*)&kpA[j];
                float4 pB4 = *(const float4*)&kpB[j];
                float4 nA4 = *(const float4*)&knA[j];
                float4 nB4 = *(const float4*)&knB[j];
                M[j]     = fmaf(gsA, pA4.x, M[j]);
                M[j]     = fmaf(gsB, pB4.x, M[j]);
                v0 = fmaf(M[j], nA4.x, v0);  u0 = fmaf(M[j], nB4.x, u0);
                M[j + 1] = fmaf(gsA, pA4.y, M[j + 1]);
                M[j + 1] = fmaf(gsB, pB4.y, M[j + 1]);
                v1 = fmaf(M[j + 1], nA4.y, v1);  u1 = fmaf(M[j + 1], nB4.y, u1);
                M[j + 2] = fmaf(gsA, pA4.z, M[j + 2]);
                M[j + 2] = fmaf(gsB, pB4.z, M[j + 2]);
                v2 = fmaf(M[j + 2], nA4.z, v2);  u2 = fmaf(M[j + 2], nB4.z, u2);
                M[j + 3] = fmaf(gsA, pA4.w, M[j + 3]);
                M[j + 3] = fmaf(gsB, pB4.w, M[j + 3]);
                v3 = fmaf(M[j + 3], nA4.w, v3);  u3 = fmaf(M[j + 3], nB4.w, u3);
            }
            a0 = (v0 + v1) + (v2 + v3);   // M_{t-1}@k^{t+2}
            a1 = (u0 + u1) + (u2 + u3);   // M_{t-1}@k^{t+3}
        }

        // ONE barrier per two steps; resolve both gates
        __syncthreads();
        float4 oth = wsum[par][w ^ 1];
        float A = pA + oth.x, Bs = pB + oth.y, C = pC + oth.z;
        int gate0 = A >= m0.y;
        float c  = m1.x * m0.x * m0.z;        // rinv_{t+1}*rinv_t*D(t,t+1)
        float cg = gate0 ? c : 0.f;
        float n1 = fmaf(cg * cg, A, Bs) - 2.f * cg * C;
        int gate1 = n1 >= m1.y;
        float err1 = fmaf(-cg, err0, e0);
        gsA = gate0 ? err0 * m0.x : 0.f;      // gs_t
        gsB = gate1 ? err1 * m1.x : 0.f;      // gs_{t+1}
        // shift pipelines
        mA = m0; mB = m1; m0 = mN0; m1 = mN1;
        d3p = d3n;
        kc0 = xA; kc1 = xB; xA = y0; xB = y1;
    }

    // trailing single step t = 1022
    // state: M = M_{1019}; pending gs_{1020}=gsA, gs_{1021}=gsB;
    // a0 = M_{1019}@k^{1022}, a1 = M_{1019}@k^{1023};
    // mA=meta[1020], mB=meta[1021], m0=meta[1022], d3p=D(1020,1023).
    {
        float vpk = fmaf(gsA, mA.w, fmaf(gsB, mB.z, a0));
        float err = fmaf(-m0.x, vpk, kc0);             // kc0 = k^{1022}_i
        float perr = err * err;
        #pragma unroll
        for (int off = 16; off; off >>= 1)
            perr += __shfl_xor_sync(0xffffffffu, perr, off);
        if ((i & 31) == 0) wsum2[w] = perr;
        __syncthreads();
        float errsum = perr + wsum2[w ^ 1];
        int gate = errsum >= m0.y;
        float gsC = gate ? err * m0.x : 0.f;           // gs_{1022}
        // read = M_{1022}@q = a1 + gsA*D(1020,1023) + gsB*D(1021,1023) + gsC*D(1022,1023)
        float readv = fmaf(gsC, m0.z, fmaf(gsB, mB.w, fmaf(gsA, d3p, a1)));
        rds[i] = readv;
    }
    __syncthreads();

    // r2[b][i] = read . rpW[:, i] + rpb[i]
    float acc = rpb[i];
    #pragma unroll 8
    for (int j = 0; j < 64; j++) acc = fmaf(rds[j], rpW[j * HH + i], acc);
    g_r2[b * HH + i] = acc;
}

// ---------------------------------------------------------------------------
// Kernel 3: out[b][v] (round-13 measured-best: float2, 8 groups x 8 batches)
// ---------------------------------------------------------------------------
__global__ void __launch_bounds__(512, 2) k3_out(const float* __restrict__ outW,
                                                 const float* __restrict__ outb,
                                                 float* __restrict__ out) {
    __shared__ float r2s[64 * 64];
    const int tid = threadIdx.x;
    for (int idx = tid; idx < 64 * 64; idx += 512) r2s[idx] = g_r2[idx];
    __syncthreads();

    const int vl = tid & 63;
    const int g  = tid >> 6;
    const int v2 = blockIdx.x * 64 + vl;
    const int b0 = g * 8;

    const float2* outW2 = (const float2*)outW;
    float2 acc[8];
    #pragma unroll
    for (int bb = 0; bb < 8; bb++) acc[bb] = make_float2(0.f, 0.f);

    #pragma unroll 8
    for (int j = 0; j < 64; j++) {
        float2 wv = outW2[j * (VV / 2) + v2];
        #pragma unroll
        for (int bb = 0; bb < 8; bb++) {
            float r = r2s[(b0 + bb) * 64 + j];
            acc[bb].x = fmaf(r, wv.x, acc[bb].x);
            acc[bb].y = fmaf(r, wv.y, acc[bb].y);
        }
    }
    float2 ob = ((const float2*)outb)[v2];
    float2* out2 = (float2*)out;
    #pragma unroll
    for (int bb = 0; bb < 8; bb++) {
        float2 r = acc[bb];
        r.x += ob.x; r.y += ob.y;
        out2[(b0 + bb) * (VV / 2) + v2] = r;
    }
}

// ---------------------------------------------------------------------------
extern "C" void kernel_launch(void* const* d_in, const int* in_sizes, int n_in,
                              void* d_out, int out_size) {
    const int*   seq   = (const int*)d_in[0];
    const float* embed = (const float*)d_in[1];
    const float* W1    = (const float*)d_in[2];
    const float* b1    = (const float*)d_in[3];
    const float* W2    = (const float*)d_in[4];
    const float* b2    = (const float*)d_in[5];
    const float* gamma = (const float*)d_in[6];
    const float* beta  = (const float*)d_in[7];
    const float* kpW   = (const float*)d_in[8];
    const float* rpW   = (const float*)d_in[9];
    const float* rpb   = (const float*)d_in[10];
    const float* outW  = (const float*)d_in[11];
    const float* outb  = (const float*)d_in[12];
    float* out = (float*)d_out;

    const int smem1 = (TOK * HPAD + TOK * H2 + HH * H2
                       + H2 + 3 * HH) * (int)sizeof(float);
    cudaFuncSetAttribute(k1_frontend, cudaFuncAttributeMaxDynamicSharedMemorySize, smem1);
    cudaFuncSetAttribute(k1_frontend, cudaFuncAttributePreferredSharedMemoryCarveout, 100);

    k1_frontend<<<(BB * LL) / TOK, 256, smem1>>>(seq, embed, W1, b1, W2, b2,
                                                 gamma, beta, kpW);
    k1b_meta<<<(BB * LL) / 8, 256>>>();
    k2_scan<<<BB, 64>>>(rpW, rpb);
    k3_out<<<VV / 128, 512>>>(outW, outb, out);
}

// round 15
// speedup vs baseline: 1.3379x; 1.3379x over previous
#include <cuda_runtime.h>
#include <cuda_bf16.h>
#include <math.h>

#define BB 64
#define LL 1024
#define HH 64
#define H2 128
#define VV 32000
#define TOK 64
#define HPAD 68

// Scratch (device globals; no allocation allowed; zero-initialized)
__device__ float  g_kall[BB * LL * HH];   // 16 MB
__device__ float4 g_meta[BB * LL];        // (rinv, 0.16*kk, D(t,t+1), D(t,t+2))
__device__ float  g_d3[BB * LL];          // D(t, t+3)
__device__ float  g_r2[BB * HH];

// ---------------------------------------------------------------------------
// Kernel 1: per-token front-end (round-12 WIN config) — unchanged.
// ---------------------------------------------------------------------------
__global__ void __launch_bounds__(256, 2) k1_frontend(
        const int* __restrict__ seq, const float* __restrict__ embed,
        const float* __restrict__ W1, const float* __restrict__ b1,
        const float* __restrict__ W2, const float* __restrict__ b2,
        const float* __restrict__ gamma, const float* __restrict__ beta,
        const float* __restrict__ kpW) {
    extern __shared__ float sm[];
    float* h_sm = sm;                      // TOK * HPAD
    float* u_sm = h_sm + TOK * HPAD;       // 64 * 128
    float* wbuf = u_sm + TOK * H2;         // 8192 (W1 / W2 / kpW)
    float* b1s  = wbuf + HH * H2;          // 128
    float* b2s  = b1s + H2;                // 64
    float* gsm  = b2s + HH;                // 64
    float* bsm  = gsm + HH;                // 64

    const int tid  = threadIdx.x;
    const int tok0 = blockIdx.x * TOK;

    if (tid < H2) b1s[tid] = b1[tid];
    if (tid < HH) { b2s[tid] = b2[tid]; gsm[tid] = gamma[tid]; bsm[tid] = beta[tid]; }
    {
        const float4* w4 = (const float4*)W1;
        float4* d4 = (float4*)wbuf;
        #pragma unroll
        for (int k = 0; k < 8; k++) d4[tid + 256 * k] = w4[tid + 256 * k];
    }
    #pragma unroll
    for (int k = 0; k < 16; k++) {
        int idx = tid + 256 * k;
        int t = idx >> 6, j = idx & 63;
        int row = seq[tok0 + t];
        h_sm[t * HPAD + j] = embed[row * HH + j];
    }
    __syncthreads();

    const int tt = tid >> 4;
    const int ct = tid & 15;

    // GEMM1
    {
        const int r0 = tt * 4, c0 = ct * 8;
        float acc[4][8];
        #pragma unroll
        for (int r = 0; r < 4; r++)
            #pragma unroll
            for (int c = 0; c < 8; c++) acc[r][c] = 0.f;
        #pragma unroll 2
        for (int j4 = 0; j4 < HH; j4 += 4) {
            float hv[4][4];
            #pragma unroll
            for (int r = 0; r < 4; r++)
                *(float4*)hv[r] = *(const float4*)&h_sm[(r0 + r) * HPAD + j4];
            #pragma unroll
            for (int jj = 0; jj < 4; jj++) {
                float4 wA = *(const float4*)&wbuf[(j4 + jj) * H2 + c0];
                float4 wB = *(const float4*)&wbuf[(j4 + jj) * H2 + c0 + 4];
                #pragma unroll
                for (int r = 0; r < 4; r++) {
                    float hvv = hv[r][jj];
                    acc[r][0] = fmaf(hvv, wA.x, acc[r][0]);
                    acc[r][1] = fmaf(hvv, wA.y, acc[r][1]);
                    acc[r][2] = fmaf(hvv, wA.z, acc[r][2]);
                    acc[r][3] = fmaf(hvv, wA.w, acc[r][3]);
                    acc[r][4] = fmaf(hvv, wB.x, acc[r][4]);
                    acc[r][5] = fmaf(hvv, wB.y, acc[r][5]);
                    acc[r][6] = fmaf(hvv, wB.z, acc[r][6]);
                    acc[r][7] = fmaf(hvv, wB.w, acc[r][7]);
                }
            }
        }
        #pragma unroll
        for (int r = 0; r < 4; r++)
            #pragma unroll
            for (int c = 0; c < 8; c++)
                u_sm[(r0 + r) * H2 + c0 + c] = fmaxf(acc[r][c] + b1s[c0 + c], 0.f);
    }
    __syncthreads();

    // load W2 over W1
    {
        const float4* w4 = (const float4*)W2;
        float4* d4 = (float4*)wbuf;
        #pragma unroll
        for (int k = 0; k < 8; k++) d4[tid + 256 * k] = w4[tid + 256 * k];
    }
    __syncthreads();

    // GEMM2 + residual
    {
        const int r0 = tt * 4, c0 = ct * 4;
        float acc[4][4];
        #pragma unroll
        for (int r = 0; r < 4; r++)
            #pragma unroll
            for (int c = 0; c < 4; c++) acc[r][c] = 0.f;
        #pragma unroll 2
        for (int j4 = 0; j4 < H2; j4 += 4) {
            float uv[4][4];
            #pragma unroll
            for (int r = 0; r < 4; r++)
                *(float4*)uv[r] = *(const float4*)&u_sm[(r0 + r) * H2 + j4];
            #pragma unroll
            for (int jj = 0; jj < 4; jj++) {
                float4 w = *(const float4*)&wbuf[(j4 + jj) * HH + c0];
                #pragma unroll
                for (int r = 0; r < 4; r++) {
                    float uvv = uv[r][jj];
                    acc[r][0] = fmaf(uvv, w.x, acc[r][0]);
                    acc[r][1] = fmaf(uvv, w.y, acc[r][1]);
                    acc[r][2] = fmaf(uvv, w.z, acc[r][2]);
                    acc[r][3] = fmaf(uvv, w.w, acc[r][3]);
                }
            }
        }
        #pragma unroll
        for (int r = 0; r < 4; r++)
            #pragma unroll
            for (int c = 0; c < 4; c++)
                h_sm[(r0 + r) * HPAD + c0 + c] += acc[r][c] + b2s[c0 + c];
    }
    __syncthreads();

    // LN (4 threads/token) + load kpW
    {
        const int tq  = tid >> 2;
        const int sub = tid & 3;
        const int j0  = sub * 16;
        float s = 0.f, ss = 0.f;
        #pragma unroll 4
        for (int j = j0; j < j0 + 16; j++) {
            float x = h_sm[tq * HPAD + j];
            s += x; ss += x * x;
        }
        s  += __shfl_xor_sync(0xffffffffu, s, 1);
        ss += __shfl_xor_sync(0xffffffffu, ss, 1);
        s  += __shfl_xor_sync(0xffffffffu, s, 2);
        ss += __shfl_xor_sync(0xffffffffu, ss, 2);
        float mu = s * (1.f / HH);
        float var = ss * (1.f / HH) - mu * mu;
        float rs = rsqrtf(var + 1e-5f);
        #pragma unroll 4
        for (int j = j0; j < j0 + 16; j++) {
            float x = h_sm[tq * HPAD + j];
            h_sm[tq * HPAD + j] = (x - mu) * rs * gsm[j] + bsm[j];
        }
        const float4* w4 = (const float4*)kpW;
        float4* d4 = (float4*)wbuf;
        #pragma unroll
        for (int k = 0; k < 4; k++) d4[tid + 256 * k] = w4[tid + 256 * k];
    }
    __syncthreads();

    // GEMM3 -> g_kall
    {
        const int r0 = tt * 4, c0 = ct * 4;
        float acc[4][4];
        #pragma unroll
        for (int r = 0; r < 4; r++)
            #pragma unroll
            for (int c = 0; c < 4; c++) acc[r][c] = 0.f;
        #pragma unroll 2
        for (int j4 = 0; j4 < HH; j4 += 4) {
            float hv[4][4];
            #pragma unroll
            for (int r = 0; r < 4; r++)
                *(float4*)hv[r] = *(const float4*)&h_sm[(r0 + r) * HPAD + j4];
            #pragma unroll
            for (int jj = 0; jj < 4; jj++) {
                float4 w = *(const float4*)&wbuf[(j4 + jj) * HH + c0];
                #pragma unroll
                for (int r = 0; r < 4; r++) {
                    float hvv = hv[r][jj];
                    acc[r][0] = fmaf(hvv, w.x, acc[r][0]);
                    acc[r][1] = fmaf(hvv, w.y, acc[r][1]);
                    acc[r][2] = fmaf(hvv, w.z, acc[r][2]);
                    acc[r][3] = fmaf(hvv, w.w, acc[r][3]);
                }
            }
        }
        #pragma unroll
        for (int r = 0; r < 4; r++)
            #pragma unroll
            for (int c = 0; c < 4; c++)
                g_kall[(tok0 + r0 + r) * HH + c0 + c] = acc[r][c];
    }
}

// ---------------------------------------------------------------------------
// Kernel 1b: per-(b,t): g_meta = (rinv, 0.16*kk, D(t,t+1), D(t,t+2)),
//            g_d3 = D(t,t+3).
// ---------------------------------------------------------------------------
__global__ void k1b_meta() {
    const int g    = blockIdx.x * 8 + (threadIdx.x >> 5);
    const int lane = threadIdx.x & 31;
    const int b = g >> 10, t = g & 1023;
    if (t >= LL - 1) return;
    const float* kt = g_kall + (b * LL + t) * HH;
    float2 k0 = *(const float2*)&kt[lane * 2];
    float2 k1 = *(const float2*)&kt[HH + lane * 2];
    float2 k2v = make_float2(0.f, 0.f);
    float2 k3v = make_float2(0.f, 0.f);
    if (t + 2 <= LL - 1) k2v = *(const float2*)&kt[2 * HH + lane * 2];
    if (t + 3 <= LL - 1) k3v = *(const float2*)&kt[3 * HH + lane * 2];
    float pkk = k0.x * k0.x + k0.y * k0.y;
    float pd1 = k0.x * k1.x + k0.y * k1.y;
    float pd2 = k0.x * k2v.x + k0.y * k2v.y;
    float pd3 = k0.x * k3v.x + k0.y * k3v.y;
    #pragma unroll
    for (int off = 16; off; off >>= 1) {
        pkk += __shfl_xor_sync(0xffffffffu, pkk, off);
        pd1 += __shfl_xor_sync(0xffffffffu, pd1, off);
        pd2 += __shfl_xor_sync(0xffffffffu, pd2, off);
        pd3 += __shfl_xor_sync(0xffffffffu, pd3, off);
    }
    if (lane == 0) {
        float rinv = 1.0f / fmaxf(sqrtf(pkk), 1e-12f);
        g_meta[b * LL + t] = make_float4(rinv, 0.16f * pkk, pd1, pd2);
        g_d3[b * LL + t] = pd3;
    }
}

// ---------------------------------------------------------------------------
// Kernel 2: TWO-STEP fused scan v2 — one 3-value butterfly + ONE barrier per
// two steps (round-14 algebra, which verified correct), but pending updates
// are applied under BLOCK-UNIFORM branches (round-13's measured-good
// conditional), and the matvec pass is separate (only 2 live float4 streams).
// ---------------------------------------------------------------------------
__global__ void __launch_bounds__(64, 1) k2_scan(const float* __restrict__ rpW,
                                                 const float* __restrict__ rpb) {
    const int b = blockIdx.x;
    const int i = threadIdx.x;
    const int w = i >> 5;
    __shared__ __align__(16) float kbuf[8][64];
    __shared__ __align__(16) float4 wsum[2][2];   // [parity][warp] = (A,B,C,-)
    __shared__ float wsum2[2];                    // trailing step
    __shared__ float rds[64];

    float M[64];
    #pragma unroll
    for (int j = 0; j < 64; j++) M[j] = 0.f;

    const float*  kb = g_kall + b * LL * HH;
    const float4* mb = g_meta + b * LL;
    const float*  db = g_d3  + b * LL;

    // zero ring (slots 4..7 read as k^{t-2}/k^{t-1} with gs=0 early on)
    #pragma unroll
    for (int sl = 0; sl < 8; sl++) kbuf[sl][i] = 0.f;

    float kc0 = kb[i];                // k^t_i   (t=0)
    float kc1 = kb[HH + i];           // k^{t+1}_i
    float xA  = kb[2 * HH + i];       // k^{t+2}_i
    float xB  = kb[3 * HH + i];       // k^{t+3}_i
    kbuf[0][i] = kc0;
    kbuf[1][i] = kc1;
    kbuf[2][i] = xA;
    kbuf[3][i] = xB;

    float4 mA = make_float4(0.f, 0.f, 0.f, 0.f);  // meta[t-2]
    float4 mB = make_float4(0.f, 0.f, 0.f, 0.f);  // meta[t-1]
    float4 m0 = mb[0];                            // meta[t]
    float4 m1 = mb[1];                            // meta[t+1]
    float  d3p = 0.f;                             // D(t-2, t+1)
    float  a0 = 0.f, a1 = 0.f;                    // M_{t-3}@k^t, M_{t-3}@k^{t+1}
    float  gsA = 0.f, gsB = 0.f;                  // gs_{t-2,i}, gs_{t-1,i}
    int    fA = 0, fB = 0;                        // gate flags (block-uniform)
    __syncthreads();

    for (int t = 0; t < LL - 2; t += 2) {
        const int par = (t >> 1) & 1;
        // prefetches for t+4 / t+5 and meta pipeline
        float y0 = (t + 4 <= LL - 1) ? kb[(t + 4) * HH + i] : 0.f;
        float y1 = (t + 5 <= LL - 1) ? kb[(t + 5) * HH + i] : 0.f;
        float4 mN0 = mb[t + 2];
        float4 mN1 = mb[t + 3];       // mb[1023] is zero-init, never consumed
        float  d3n = db[t];           // D(t, t+3) -> next iteration's d3p

        // per-thread errors for steps t and t+1 (critical chain)
        float vpk0 = fmaf(gsA, mA.w, fmaf(gsB, mB.z, a0));
        float err0 = fmaf(-m0.x, vpk0, kc0);
        float vpk1 = fmaf(gsA, d3p, fmaf(gsB, mB.w, a1));
        float e0   = fmaf(-m1.x, vpk1, kc1);

        float pA = err0 * err0, pB = e0 * e0, pC = err0 * e0;
        #pragma unroll
        for (int off = 16; off; off >>= 1) {
            pA += __shfl_xor_sync(0xffffffffu, pA, off);
            pB += __shfl_xor_sync(0xffffffffu, pB, off);
            pC += __shfl_xor_sync(0xffffffffu, pC, off);
        }
        if ((i & 31) == 0) wsum[par][w] = make_float4(pA, pB, pC, 0.f);

        // publish k^{t+4}, k^{t+5} (overwrite dead slots t-4, t-3)
        kbuf[(t + 4) & 7][i] = y0;
        kbuf[(t + 5) & 7][i] = y1;

        // conditional pending updates (block-uniform branches, round-13 style)
        if (fA) {
            const float* kpA = kbuf[(t - 2) & 7];
            #pragma unroll
            for (int j = 0; j < 64; j += 4) {
                float4 k4 = *(const float4*)&kpA[j];
                M[j]     = fmaf(gsA, k4.x, M[j]);
                M[j + 1] = fmaf(gsA, k4.y, M[j + 1]);
                M[j + 2] = fmaf(gsA, k4.z, M[j + 2]);
                M[j + 3] = fmaf(gsA, k4.w, M[j + 3]);
            }
        }
        if (fB) {
            const float* kpB = kbuf[(t - 1) & 7];
            #pragma unroll
            for (int j = 0; j < 64; j += 4) {
                float4 k4 = *(const float4*)&kpB[j];
                M[j]     = fmaf(gsB, k4.x, M[j]);
                M[j + 1] = fmaf(gsB, k4.y, M[j + 1]);
                M[j + 2] = fmaf(gsB, k4.z, M[j + 2]);
                M[j + 3] = fmaf(gsB, k4.w, M[j + 3]);
            }
        }

        // dual matvec pass: a0 = M_{t-1}@k^{t+2}, a1 = M_{t-1}@k^{t+3}
        {
            const float* knA = kbuf[(t + 2) & 7];
            const float* knB = kbuf[(t + 3) & 7];
            float v0 = 0.f, v1 = 0.f, v2 = 0.f, v3 = 0.f;
            float u0 = 0.f, u1 = 0.f, u2 = 0.f, u3 = 0.f;
            #pragma unroll
            for (int j = 0; j < 64; j += 4) {
                float4 nA4 = *(const float4*)&knA[j];
                float4 nB4 = *(const float4*)&knB[j];
                v0 = fmaf(M[j],     nA4.x, v0);  u0 = fmaf(M[j],     nB4.x, u0);
                v1 = fmaf(M[j + 1], nA4.y, v1);  u1 = fmaf(M[j + 1], nB4.y, u1);
                v2 = fmaf(M[j + 2], nA4.z, v2);  u2 = fmaf(M[j + 2], nB4.z, u2);
                v3 = fmaf(M[j + 3], nA4.w, v3);  u3 = fmaf(M[j + 3], nB4.w, u3);
            }
            a0 = (v0 + v1) + (v2 + v3);
            a1 = (u0 + u1) + (u2 + u3);
        }

        // ONE barrier per two steps; resolve both gates
        __syncthreads();
        float4 oth = wsum[par][w ^ 1];
        float A = pA + oth.x, Bs = pB + oth.y, C = pC + oth.z;
        int gate0 = A >= m0.y;
        float c  = m1.x * m0.x * m0.z;        // rinv_{t+1}*rinv_t*D(t,t+1)
        float cg = gate0 ? c : 0.f;
        float n1 = fmaf(cg * cg, A, Bs) - 2.f * cg * C;
        int gate1 = n1 >= m1.y;
        float err1 = fmaf(-cg, err0, e0);
        gsA = gate0 ? err0 * m0.x : 0.f;      // gs_t
        gsB = gate1 ? err1 * m1.x : 0.f;      // gs_{t+1}
        fA = gate0; fB = gate1;
        // shift pipelines
        mA = m0; mB = m1; m0 = mN0; m1 = mN1;
        d3p = d3n;
        kc0 = xA; kc1 = xB; xA = y0; xB = y1;
    }

    // trailing single step t = 1022
    // state: M = M_{1019}; pending gs_{1020}=gsA, gs_{1021}=gsB;
    // a0 = M_{1019}@k^{1022}, a1 = M_{1019}@k^{1023};
    // mA=meta[1020], mB=meta[1021], m0=meta[1022], d3p=D(1020,1023).
    {
        float vpk = fmaf(gsA, mA.w, fmaf(gsB, mB.z, a0));
        float err = fmaf(-m0.x, vpk, kc0);             // kc0 = k^{1022}_i
        float perr = err * err;
        #pragma unroll
        for (int off = 16; off; off >>= 1)
            perr += __shfl_xor_sync(0xffffffffu, perr, off);
        if ((i & 31) == 0) wsum2[w] = perr;
        __syncthreads();
        float errsum = perr + wsum2[w ^ 1];
        int gate = errsum >= m0.y;
        float gsC = gate ? err * m0.x : 0.f;           // gs_{1022}
        // read = M_{1022}@q = a1 + gsA*D(1020,1023) + gsB*D(1021,1023) + gsC*D(1022,1023)
        float readv = fmaf(gsC, m0.z, fmaf(gsB, mB.w, fmaf(gsA, d3p, a1)));
        rds[i] = readv;
    }
    __syncthreads();

    // r2[b][i] = read . rpW[:, i] + rpb[i]
    float acc = rpb[i];
    #pragma unroll 8
    for (int j = 0; j < 64; j++) acc = fmaf(rds[j], rpW[j * HH + i], acc);
    g_r2[b * HH + i] = acc;
}

// ---------------------------------------------------------------------------
// Kernel 3: out[b][v] (round-13 measured-best: float2, 8 groups x 8 batches)
// ---------------------------------------------------------------------------
__global__ void __launch_bounds__(512, 2) k3_out(const float* __restrict__ outW,
                                                 const float* __restrict__ outb,
                                                 float* __restrict__ out) {
    __shared__ float r2s[64 * 64];
    const int tid = threadIdx.x;
    for (int idx = tid; idx < 64 * 64; idx += 512) r2s[idx] = g_r2[idx];
    __syncthreads();

    const int vl = tid & 63;
    const int g  = tid >> 6;
    const int v2 = blockIdx.x * 64 + vl;
    const int b0 = g * 8;

    const float2* outW2 = (const float2*)outW;
    float2 acc[8];
    #pragma unroll
    for (int bb = 0; bb < 8; bb++) acc[bb] = make_float2(0.f, 0.f);

    #pragma unroll 8
    for (int j = 0; j < 64; j++) {
        float2 wv = outW2[j * (VV / 2) + v2];
        #pragma unroll
        for (int bb = 0; bb < 8; bb++) {
            float r = r2s[(b0 + bb) * 64 + j];
            acc[bb].x = fmaf(r, wv.x, acc[bb].x);
            acc[bb].y = fmaf(r, wv.y, acc[bb].y);
        }
    }
    float2 ob = ((const float2*)outb)[v2];
    float2* out2 = (float2*)out;
    #pragma unroll
    for (int bb = 0; bb < 8; bb++) {
        float2 r = acc[bb];
        r.x += ob.x; r.y += ob.y;
        out2[(b0 + bb) * (VV / 2) + v2] = r;
    }
}

// ---------------------------------------------------------------------------
extern "C" void kernel_launch(void* const* d_in, const int* in_sizes, int n_in,
                              void* d_out, int out_size) {
    const int*   seq   = (const int*)d_in[0];
    const float* embed = (const float*)d_in[1];
    const float* W1    = (const float*)d_in[2];
    const float* b1    = (const float*)d_in[3];
    const float* W2    = (const float*)d_in[4];
    const float* b2    = (const float*)d_in[5];
    const float* gamma = (const float*)d_in[6];
    const float* beta  = (const float*)d_in[7];
    const float* kpW   = (const float*)d_in[8];
    const float* rpW   = (const float*)d_in[9];
    const float* rpb   = (const float*)d_in[10];
    const float* outW  = (const float*)d_in[11];
    const float* outb  = (const float*)d_in[12];
    float* out = (float*)d_out;

    const int smem1 = (TOK * HPAD + TOK * H2 + HH * H2
                       + H2 + 3 * HH) * (int)sizeof(float);
    cudaFuncSetAttribute(k1_frontend, cudaFuncAttributeMaxDynamicSharedMemorySize, smem1);
    cudaFuncSetAttribute(k1_frontend, cudaFuncAttributePreferredSharedMemoryCarveout, 100);

    k1_frontend<<<(BB * LL) / TOK, 256, smem1>>>(seq, embed, W1, b1, W2, b2,
                                                 gamma, beta, kpW);
    k1b_meta<<<(BB * LL) / 8, 256>>>();
    k2_scan<<<BB, 64>>>(rpW, rpb);
    k3_out<<<VV / 128, 512>>>(outW, outb, out);
}